// round 1
// baseline (speedup 1.0000x reference)
#include <cuda_runtime.h>

#define BB 8
#define HH 512
#define WW 512
#define NPIX (BB*HH*WW)

// ---------------- scratch (static device globals; no allocation) ----------------
__device__ __align__(16) float g_edges[NPIX];        // 8 MB
__device__ __align__(16) float g_c0[8*NPIX];         // 64 MB, layout [b][ic][y][x]
__device__ __align__(16) float g_c1[8*NPIX];         // 64 MB, layout [b][oc][y][x]
__device__ __align__(16) float g_kpre[NPIX];         // 8 MB
__device__ float g_DP[72];                           // folded depthwise∘pointwise, [tap][c]
__device__ float g_K2S[72];                          // curve_2 summed over 16 oc, [tap][ic]

// zero-padded load from a 512x512 plane
__device__ __forceinline__ float ldz(const float* __restrict__ p, int y, int x) {
    return ((unsigned)y < 512u && (unsigned)x < 512u) ? __ldg(p + y*512 + x) : 0.f;
}

// ---------------- setup: fold small kernels ----------------
__global__ void setup_k(const float* __restrict__ dw,   // (3,3,1,8)
                        const float* __restrict__ pw,   // (1,1,8,8)
                        const float* __restrict__ c2)   // (3,3,8,16)
{
    int t = threadIdx.x;
    if (t < 72) {
        int tap = t >> 3, c = t & 7;
        float s = 0.f;
        #pragma unroll
        for (int j = 0; j < 8; j++) s = fmaf(dw[tap*8+j], pw[j*8+c], s);
        g_DP[t] = s;
        float s2 = 0.f;
        #pragma unroll
        for (int oc = 0; oc < 16; oc++) s2 += c2[t*16+oc];
        g_K2S[t] = s2;
    }
}

// ---------------- edges: softsign(sum(relu(conv3x3_DP(image)))) ----------------
__global__ __launch_bounds__(256) void edges_k(const float* __restrict__ img)
{
    __shared__ float sDP[72];
    if (threadIdx.x < 72) sDP[threadIdx.x] = g_DP[threadIdx.x];
    __syncthreads();

    int idx = blockIdx.x * 256 + threadIdx.x;
    int x = idx & 511, y = (idx >> 9) & 511, b = idx >> 18;
    const float* im = img + b * (HH*WW);

    float acc[8] = {0,0,0,0,0,0,0,0};
    #pragma unroll
    for (int ky = 0; ky < 3; ky++) {
        #pragma unroll
        for (int kx = 0; kx < 3; kx++) {
            float v = ldz(im, y + ky - 1, x + kx - 1);
            int tap = ky*3 + kx;
            #pragma unroll
            for (int c = 0; c < 8; c++) acc[c] = fmaf(v, sDP[tap*8+c], acc[c]);
        }
    }
    float s = 0.f;
    #pragma unroll
    for (int c = 0; c < 8; c++) s += fmaxf(acc[c], 0.f);
    g_edges[idx] = s / (1.f + fabsf(s));   // soft_sign
}

// ---------------- c0: conv5x5 (1->8) of u, planar output ----------------
__global__ __launch_bounds__(256) void c0_k(const float* __restrict__ u,
                                            const float* __restrict__ k0)  // (5,5,1,8)
{
    __shared__ float sW[200];
    for (int i = threadIdx.x; i < 200; i += 256) sW[i] = k0[i];
    __syncthreads();

    int idx = blockIdx.x * 256 + threadIdx.x;
    int x = idx & 511, y = (idx >> 9) & 511, b = idx >> 18;
    const float* up = u + b * (HH*WW);

    float acc[8] = {0,0,0,0,0,0,0,0};
    #pragma unroll
    for (int ky = 0; ky < 5; ky++) {
        #pragma unroll
        for (int kx = 0; kx < 5; kx++) {
            float v = ldz(up, y + ky - 2, x + kx - 2);
            int tap = ky*5 + kx;
            #pragma unroll
            for (int oc = 0; oc < 8; oc++) acc[oc] = fmaf(v, sW[tap*8+oc], acc[oc]);
        }
    }
    #pragma unroll
    for (int oc = 0; oc < 8; oc++)
        g_c0[((b*8 + oc)*512 + y)*512 + x] = acc[oc];
}

// ---------------- c1: conv5x5 (8->8), shared-tiled, 4 px/thread ----------------
// block (8,32): thread (tx,ty) computes output row ty, cols tx*4..tx*4+3 of a 32x32 tile
__global__ __launch_bounds__(256) void c1_k(const float* __restrict__ k1)  // (5,5,8,8)
{
    __shared__ float  sIn[8][36][37];   // [ic][row][col], 37 => conflict-free (37 % 4 == 1)
    __shared__ float4 sW[400];          // 25 taps x 8 ic x 8 oc = 1600 f = 400 float4

    int b  = blockIdx.z;
    int x0 = blockIdx.x << 5, y0 = blockIdx.y << 5;
    int tx = threadIdx.x, ty = threadIdx.y;
    int tid = ty * 8 + tx;

    const float4* k14 = (const float4*)k1;
    for (int i = tid; i < 400; i += 256) sW[i] = k14[i];

    for (int i = tid; i < 8*36*36; i += 256) {
        int c  = i % 36;
        int rr = i / 36;
        int r  = rr % 36;
        int ic = rr / 36;
        int gy = y0 + r - 2, gx = x0 + c - 2;
        float v = 0.f;
        if ((unsigned)gy < 512u && (unsigned)gx < 512u)
            v = g_c0[((b*8 + ic)*512 + gy)*512 + gx];
        sIn[ic][r][c] = v;
    }
    __syncthreads();

    float acc[4][8];
    #pragma unroll
    for (int d = 0; d < 4; d++)
        #pragma unroll
        for (int o = 0; o < 8; o++) acc[d][o] = 0.f;

    int bx = tx << 2;
    #pragma unroll 1
    for (int ky = 0; ky < 5; ky++) {
        #pragma unroll 1
        for (int kx = 0; kx < 5; kx++) {
            const float4* wp = sW + (ky*5 + kx)*16;   // 8 ic x 2 float4
            #pragma unroll
            for (int ic = 0; ic < 8; ic++) {
                float4 w0 = wp[2*ic];
                float4 w1 = wp[2*ic + 1];
                const float* ip = &sIn[ic][ty + ky][bx + kx];
                #pragma unroll
                for (int d = 0; d < 4; d++) {
                    float iv = ip[d];
                    acc[d][0] = fmaf(iv, w0.x, acc[d][0]);
                    acc[d][1] = fmaf(iv, w0.y, acc[d][1]);
                    acc[d][2] = fmaf(iv, w0.z, acc[d][2]);
                    acc[d][3] = fmaf(iv, w0.w, acc[d][3]);
                    acc[d][4] = fmaf(iv, w1.x, acc[d][4]);
                    acc[d][5] = fmaf(iv, w1.y, acc[d][5]);
                    acc[d][6] = fmaf(iv, w1.z, acc[d][6]);
                    acc[d][7] = fmaf(iv, w1.w, acc[d][7]);
                }
            }
        }
    }

    int yy = y0 + ty;
    #pragma unroll
    for (int oc = 0; oc < 8; oc++) {
        float4 v = make_float4(acc[0][oc], acc[1][oc], acc[2][oc], acc[3][oc]);
        *(float4*)&g_c1[((b*8 + oc)*512 + yy)*512 + (x0 + bx)] = v;
    }
}

// ---------------- c2: conv3x3 (8->1 summed) * kappa_kernel ----------------
__global__ __launch_bounds__(256) void c2_k(const float* __restrict__ kap)  // (512,512,1)
{
    __shared__ float sK[72];
    if (threadIdx.x < 72) sK[threadIdx.x] = g_K2S[threadIdx.x];
    __syncthreads();

    int idx = blockIdx.x * 256 + threadIdx.x;
    int x = idx & 511, y = (idx >> 9) & 511, b = idx >> 18;

    float s = 0.f;
    #pragma unroll
    for (int ic = 0; ic < 8; ic++) {
        const float* p = g_c1 + (b*8 + ic)*512*512;
        #pragma unroll
        for (int ky = 0; ky < 3; ky++) {
            #pragma unroll
            for (int kx = 0; kx < 3; kx++) {
                float v = ldz(p, y + ky - 1, x + kx - 1);
                s = fmaf(v, sK[(ky*3 + kx)*8 + ic], s);
            }
        }
    }
    g_kpre[idx] = s * __ldg(kap + y*512 + x);
}

// ---------------- final: grad_edges + finite diff + smoother + combine ----------------
__global__ __launch_bounds__(256) void final_k(const float* __restrict__ u,
                                               const float* __restrict__ kxw,  // (3,3,1,32)
                                               const float* __restrict__ kyw,  // (3,3,1,32)
                                               const float* __restrict__ smw,  // (5,5,1,1)
                                               float* __restrict__ out)
{
    __shared__ float sKX[288], sKY[288], sSM[25];
    for (int i = threadIdx.x; i < 288; i += 256) { sKX[i] = kxw[i]; sKY[i] = kyw[i]; }
    if (threadIdx.x < 25) sSM[threadIdx.x] = smw[threadIdx.x];
    __syncthreads();

    int idx = blockIdx.x * 256 + threadIdx.x;
    int x = idx & 511, y = (idx >> 9) & 511, b = idx >> 18;
    int base = b * (HH*WW);

    // 3x3 edges neighborhood (zero-padded)
    const float* ep = g_edges + base;
    float e[9];
    #pragma unroll
    for (int t = 0; t < 9; t++)
        e[t] = ldz(ep, y + t/3 - 1, x + (t%3) - 1);

    // grad_edges_x / grad_edges_y : sum_c relu(<e, K[:, c]>)   (always >= 0)
    float gx = 0.f, gy = 0.f;
    #pragma unroll 4
    for (int c = 0; c < 32; c++) {
        float sx = 0.f, sy = 0.f;
        #pragma unroll
        for (int t = 0; t < 9; t++) {
            sx = fmaf(e[t], sKX[t*32 + c], sx);
            sy = fmaf(e[t], sKY[t*32 + c], sy);
        }
        gx += fmaxf(sx, 0.f);
        gy += fmaxf(sy, 0.f);
    }

    // finite differences (SAME zero padding):
    //   xp = u[y][x] - u[y][x-1]   (KXP),  yp = u[y][x] - u[y+1][x] (KYP)
    // fxn = -relu(-gx) = 0 and fyn = 0 since gx,gy >= 0, so only xp/yp terms survive.
    const float* up = u + base;
    float uc = __ldg(up + y*512 + x);
    float ul = (x > 0)   ? __ldg(up + y*512 + (x-1)) : 0.f;
    float ud = (y < 511) ? __ldg(up + (y+1)*512 + x) : 0.f;
    float xp = uc - ul;
    float yp = uc - ud;

    // kappa = conv5x5(g_kpre, smoother)
    const float* kp = g_kpre + base;
    float kappa = 0.f;
    #pragma unroll
    for (int t = 0; t < 25; t++) {
        float v = ldz(kp, y + t/5 - 2, x + (t%5) - 2);
        kappa = fmaf(v, sSM[t], kappa);
    }

    out[idx] = uc + gx*xp + gy*yp + e[4] + kappa;
}

// ---------------- launch ----------------
extern "C" void kernel_launch(void* const* d_in, const int* in_sizes, int n_in,
                              void* d_out, int out_size)
{
    const float* u   = (const float*)d_in[0];
    const float* img = (const float*)d_in[1];
    const float* kx  = (const float*)d_in[2];
    const float* ky  = (const float*)d_in[3];
    const float* dw  = (const float*)d_in[4];
    const float* pw  = (const float*)d_in[5];
    const float* c0k = (const float*)d_in[6];
    const float* c1k = (const float*)d_in[7];
    const float* c2k = (const float*)d_in[8];
    const float* smk = (const float*)d_in[9];
    const float* kap = (const float*)d_in[10];
    float* out = (float*)d_out;

    const int PIX_BLOCKS = NPIX / 256;  // 8192

    setup_k<<<1, 128>>>(dw, pw, c2k);
    edges_k<<<PIX_BLOCKS, 256>>>(img);
    c0_k<<<PIX_BLOCKS, 256>>>(u, c0k);
    c1_k<<<dim3(16, 16, 8), dim3(8, 32)>>>(c1k);
    c2_k<<<PIX_BLOCKS, 256>>>(kap);
    final_k<<<PIX_BLOCKS, 256>>>(u, kx, ky, smk, out);
}

// round 2
// speedup vs baseline: 2.1881x; 2.1881x over previous
#include <cuda_runtime.h>

#define BB 8
#define HH 512
#define WW 512
#define NPIX (BB*HH*WW)

// ---------------- scratch (static device globals; no allocation) ----------------
__device__ __align__(16) float g_edges[NPIX];        // 8 MB
__device__ __align__(16) float g_c0[8*NPIX];         // band-only valid, [b][ic][y][x]
__device__ __align__(16) float g_c1[8*NPIX];         // band-only valid, [b][oc][y][x]
__device__ __align__(16) float g_kpre[NPIX];         // 8 MB
__device__ float g_DP[72];                           // depthwise∘pointwise folded, [tap][c]
__device__ float g_K2S[72];                          // curve_2 summed over 16 oc, [tap][ic]
__device__ float g_KC[121];                          // composed 11x11 kappa kernel

// zero-padded load from a 512x512 plane
__device__ __forceinline__ float ldz(const float* __restrict__ p, int y, int x) {
    return ((unsigned)y < 512u && (unsigned)x < 512u) ? __ldg(p + y*512 + x) : 0.f;
}

// ---- packed f32x2 helpers (Blackwell FFMA2: 2x fp32 FMA throughput) ----
typedef unsigned long long u64t;
__device__ __forceinline__ u64t pk2(float lo, float hi) {
    u64t r; asm("mov.b64 %0, {%1, %2};" : "=l"(r) : "f"(lo), "f"(hi)); return r;
}
__device__ __forceinline__ void upk2(u64t v, float& lo, float& hi) {
    asm("mov.b64 {%0, %1}, %2;" : "=f"(lo), "=f"(hi) : "l"(v));
}
__device__ __forceinline__ u64t fma2(u64t a, u64t b, u64t c) {
    u64t d; asm("fma.rn.f32x2 %0, %1, %2, %3;" : "=l"(d) : "l"(a), "l"(b), "l"(c)); return d;
}

// map linear index j to (y,x) inside a boundary band of width Wb
__device__ __forceinline__ void band_coord(int j, int Wb, int& y, int& x) {
    int t1 = Wb * 512;
    if (j < t1)            { y = j / 512;                x = j % 512; }
    else if (j < 2*t1)     { int k = j - t1; y = 512 - Wb + k/512; x = k % 512; }
    else {
        int k = j - 2*t1;
        int h = 512 - 2*Wb;
        int side = k / (h*Wb);
        int m = k % (h*Wb);
        y = Wb + m / Wb;
        int xx = m % Wb;
        x = side ? (512 - Wb + xx) : xx;
    }
}

// ---------------- setup: fold small kernels + compose kappa chain ----------------
// KC (11x11) = K0(5x5,1->8) ∘ K1(5x5,8->8) ∘ K2S(3x3,8->1)   (exact for interior)
__global__ void setup_k(const float* __restrict__ dw,   // (3,3,1,8)
                        const float* __restrict__ pw,   // (1,1,8,8)
                        const float* __restrict__ c2,   // (3,3,8,16)
                        const float* __restrict__ k0,   // (5,5,1,8)
                        const float* __restrict__ k1)   // (5,5,8,8)
{
    __shared__ float sK2S[72];      // [r][ic]
    __shared__ float sK12[49*8];    // [e][ic], 7x7 composed K1∘K2S
    int t = threadIdx.x;
    if (t < 72) {
        int tap = t >> 3, c = t & 7;
        float s = 0.f;
        #pragma unroll
        for (int j = 0; j < 8; j++) s = fmaf(dw[tap*8+j], pw[j*8+c], s);
        g_DP[t] = s;
        float s2 = 0.f;
        #pragma unroll
        for (int oc = 0; oc < 16; oc++) s2 += c2[t*16+oc];
        g_K2S[t] = s2;
        sK2S[t]  = s2;
    }
    __syncthreads();
    // K12[e][ic] = sum_{r,o} K1[e-r][ic][o] * K2S[r][o],  e in [0,6]^2, t=e-r in [0,4]^2
    for (int i = t; i < 49*8; i += blockDim.x) {
        int e = i >> 3, ic = i & 7;
        int ey = e / 7, ex = e % 7;
        float s = 0.f;
        for (int ry = 0; ry < 3; ry++) {
            int ty = ey - ry; if (ty < 0 || ty > 4) continue;
            for (int rx = 0; rx < 3; rx++) {
                int tx = ex - rx; if (tx < 0 || tx > 4) continue;
                const float* kp = k1 + ((ty*5+tx)*8 + ic)*8;
                const float* rp = sK2S + (ry*3+rx)*8;
                #pragma unroll
                for (int o = 0; o < 8; o++) s = fmaf(kp[o], rp[o], s);
            }
        }
        sK12[i] = s;
    }
    __syncthreads();
    // KC[d] = sum_{s,c} K0[s][c] * K12[d-s][c],  d in [0,10]^2, e=d-s in [0,6]^2
    for (int i = t; i < 121; i += blockDim.x) {
        int dy = i / 11, dx = i % 11;
        float s = 0.f;
        for (int sy = 0; sy < 5; sy++) {
            int ey = dy - sy; if (ey < 0 || ey > 6) continue;
            for (int sx = 0; sx < 5; sx++) {
                int ex = dx - sx; if (ex < 0 || ex > 6) continue;
                const float* k0p = k0 + (sy*5+sx)*8;
                const float* k12p = sK12 + (ey*7+ex)*8;
                #pragma unroll
                for (int c = 0; c < 8; c++) s = fmaf(k0p[c], k12p[c], s);
            }
        }
        g_KC[i] = s;
    }
}

// ---------------- edges: softsign(sum(relu(conv3x3_DP(image)))) ----------------
__global__ __launch_bounds__(256) void edges_k(const float* __restrict__ img)
{
    __shared__ float sDP[72];
    if (threadIdx.x < 72) sDP[threadIdx.x] = g_DP[threadIdx.x];
    __syncthreads();

    int idx = blockIdx.x * 256 + threadIdx.x;
    int x = idx & 511, y = (idx >> 9) & 511, b = idx >> 18;
    const float* im = img + b * (HH*WW);

    float acc[8] = {0,0,0,0,0,0,0,0};
    #pragma unroll
    for (int ky = 0; ky < 3; ky++) {
        #pragma unroll
        for (int kx = 0; kx < 3; kx++) {
            float v = ldz(im, y + ky - 1, x + kx - 1);
            int tap = ky*3 + kx;
            #pragma unroll
            for (int c = 0; c < 8; c++) acc[c] = fmaf(v, sDP[tap*8+c], acc[c]);
        }
    }
    float s = 0.f;
    #pragma unroll
    for (int c = 0; c < 8; c++) s += fmaxf(acc[c], 0.f);
    g_edges[idx] = s / (1.f + fabsf(s));
}

// ---------------- kc: composed 11x11 conv of u, times kappa_kernel ----------------
// block (8,32): thread (tx,ty) -> output row ty, cols tx*4..+3 of a 32x32 tile
__global__ __launch_bounds__(256) void kc_k(const float* __restrict__ u,
                                            const float* __restrict__ kap)
{
    __shared__ float sW[121];
    __shared__ float sIn[42*43];

    int b  = blockIdx.z;
    int x0 = blockIdx.x << 5, y0 = blockIdx.y << 5;
    int tx = threadIdx.x, ty = threadIdx.y;
    int tid = ty * 8 + tx;

    if (tid < 121) sW[tid] = g_KC[tid];

    const float* up = u + b * (HH*WW);
    for (int i = tid; i < 42*42; i += 256) {
        int r = i / 42, c = i % 42;
        sIn[r*43 + c] = ldz(up, y0 + r - 5, x0 + c - 5);
    }
    __syncthreads();

    int bx = tx << 2;
    float acc0 = 0.f, acc1 = 0.f, acc2 = 0.f, acc3 = 0.f;
    #pragma unroll 1
    for (int ky = 0; ky < 11; ky++) {
        const float* row = &sIn[(ty + ky)*43 + bx];
        float v[14];
        #pragma unroll
        for (int j = 0; j < 14; j++) v[j] = row[j];
        const float* wr = sW + ky*11;
        #pragma unroll
        for (int kx = 0; kx < 11; kx++) {
            float w = wr[kx];
            acc0 = fmaf(v[kx  ], w, acc0);
            acc1 = fmaf(v[kx+1], w, acc1);
            acc2 = fmaf(v[kx+2], w, acc2);
            acc3 = fmaf(v[kx+3], w, acc3);
        }
    }

    int yy = y0 + ty, xx = x0 + bx;
    float4 kv = *(const float4*)&kap[yy*512 + xx];
    float4 o = make_float4(acc0*kv.x, acc1*kv.y, acc2*kv.z, acc3*kv.w);
    *(float4*)&g_kpre[(b*HH*WW) + yy*512 + xx] = o;
}

// ---------------- boundary staged path (band widths 6 / 4 / 3) ----------------
__global__ __launch_bounds__(256) void bc0_k(const float* __restrict__ u,
                                             const float* __restrict__ k0)  // (5,5,1,8)
{
    __shared__ float sW[200];
    for (int i = threadIdx.x; i < 200; i += 256) sW[i] = k0[i];
    __syncthreads();

    const int NB = 2*6*512 + 2*500*6;   // 12144
    int i = blockIdx.x * 256 + threadIdx.x;
    if (i >= NB * BB) return;
    int b = i / NB, j = i % NB;
    int y, x; band_coord(j, 6, y, x);
    const float* up = u + b * (HH*WW);

    float acc[8] = {0,0,0,0,0,0,0,0};
    #pragma unroll
    for (int ky = 0; ky < 5; ky++)
        #pragma unroll
        for (int kx = 0; kx < 5; kx++) {
            float v = ldz(up, y + ky - 2, x + kx - 2);
            int tap = ky*5 + kx;
            #pragma unroll
            for (int oc = 0; oc < 8; oc++) acc[oc] = fmaf(v, sW[tap*8+oc], acc[oc]);
        }
    #pragma unroll
    for (int oc = 0; oc < 8; oc++)
        g_c0[((b*8 + oc)*512 + y)*512 + x] = acc[oc];
}

__global__ __launch_bounds__(256) void bc1_k(const float* __restrict__ k1)  // (5,5,8,8)
{
    __shared__ float sW[1600];
    for (int i = threadIdx.x; i < 1600; i += 256) sW[i] = k1[i];
    __syncthreads();

    const int NB = 2*4*512 + 2*504*4;   // 8128
    int i = blockIdx.x * 256 + threadIdx.x;
    if (i >= NB * BB) return;
    int b = i / NB, j = i % NB;
    int y, x; band_coord(j, 4, y, x);

    float acc[8] = {0,0,0,0,0,0,0,0};
    #pragma unroll 1
    for (int ic = 0; ic < 8; ic++) {
        const float* p = g_c0 + (b*8 + ic)*HH*WW;
        #pragma unroll
        for (int ky = 0; ky < 5; ky++)
            #pragma unroll
            for (int kx = 0; kx < 5; kx++) {
                float v = ldz(p, y + ky - 2, x + kx - 2);
                const float* wp = sW + ((ky*5 + kx)*8 + ic)*8;
                #pragma unroll
                for (int oc = 0; oc < 8; oc++) acc[oc] = fmaf(v, wp[oc], acc[oc]);
            }
    }
    #pragma unroll
    for (int oc = 0; oc < 8; oc++)
        g_c1[((b*8 + oc)*512 + y)*512 + x] = acc[oc];
}

__global__ __launch_bounds__(256) void bc2_k(const float* __restrict__ kap)
{
    __shared__ float sK[72];
    if (threadIdx.x < 72) sK[threadIdx.x] = g_K2S[threadIdx.x];
    __syncthreads();

    const int NB = 2*3*512 + 2*506*3;   // 6108
    int i = blockIdx.x * 256 + threadIdx.x;
    if (i >= NB * BB) return;
    int b = i / NB, j = i % NB;
    int y, x; band_coord(j, 3, y, x);

    float s = 0.f;
    #pragma unroll 1
    for (int ic = 0; ic < 8; ic++) {
        const float* p = g_c1 + (b*8 + ic)*HH*WW;
        #pragma unroll
        for (int ky = 0; ky < 3; ky++)
            #pragma unroll
            for (int kx = 0; kx < 3; kx++) {
                float v = ldz(p, y + ky - 1, x + kx - 1);
                s = fmaf(v, sK[(ky*3 + kx)*8 + ic], s);
            }
    }
    g_kpre[b*HH*WW + y*512 + x] = s * __ldg(kap + y*512 + x);
}

// ---------------- final: grad_edges (FFMA2, 2 px/thread) + fd + smoother ----------------
__global__ __launch_bounds__(256) void final_k(const float* __restrict__ u,
                                               const float* __restrict__ kxw,  // (3,3,1,32)
                                               const float* __restrict__ kyw,  // (3,3,1,32)
                                               const float* __restrict__ smw,  // (5,5,1,1)
                                               float* __restrict__ out)
{
    __shared__ u64t sKX2[288], sKY2[288], sSM2[25];
    for (int i = threadIdx.x; i < 288; i += 256) {
        float wx = kxw[i], wy = kyw[i];
        sKX2[i] = pk2(wx, wx);
        sKY2[i] = pk2(wy, wy);
    }
    if (threadIdx.x < 25) { float w = smw[threadIdx.x]; sSM2[threadIdx.x] = pk2(w, w); }
    __syncthreads();

    int idx2 = (blockIdx.x * 256 + threadIdx.x) * 2;   // left pixel; right = idx2+1
    int x0 = idx2 & 511, y = (idx2 >> 9) & 511, b = idx2 >> 18;
    int base = b * (HH*WW);

    // edges neighborhood: rows y-1..y+1, cols x0-1..x0+2
    const float* ep = g_edges + base;
    float E[3][4];
    #pragma unroll
    for (int dy = 0; dy < 3; dy++)
        #pragma unroll
        for (int dx = 0; dx < 4; dx++)
            E[dy][dx] = ldz(ep, y + dy - 1, x0 + dx - 1);

    u64t e2[9];
    #pragma unroll
    for (int dy = 0; dy < 3; dy++)
        #pragma unroll
        for (int dx = 0; dx < 3; dx++)
            e2[dy*3 + dx] = pk2(E[dy][dx], E[dy][dx+1]);

    float gxL = 0.f, gxR = 0.f, gyL = 0.f, gyR = 0.f;
    #pragma unroll 4
    for (int c = 0; c < 32; c++) {
        u64t sx = 0ULL, sy = 0ULL;
        #pragma unroll
        for (int t = 0; t < 9; t++) {
            sx = fma2(e2[t], sKX2[t*32 + c], sx);
            sy = fma2(e2[t], sKY2[t*32 + c], sy);
        }
        float lo, hi;
        upk2(sx, lo, hi); gxL += fmaxf(lo, 0.f); gxR += fmaxf(hi, 0.f);
        upk2(sy, lo, hi); gyL += fmaxf(lo, 0.f); gyR += fmaxf(hi, 0.f);
    }

    // smoother: conv5x5 of g_kpre, 2 px packed
    const float* kp = g_kpre + base;
    u64t kacc = 0ULL;
    #pragma unroll
    for (int dy = 0; dy < 5; dy++) {
        float P[6];
        #pragma unroll
        for (int dx = 0; dx < 6; dx++) P[dx] = ldz(kp, y + dy - 2, x0 + dx - 2);
        #pragma unroll
        for (int dx = 0; dx < 5; dx++)
            kacc = fma2(pk2(P[dx], P[dx+1]), sSM2[dy*5 + dx], kacc);
    }
    float kL, kR; upk2(kacc, kL, kR);

    // finite differences (zero SAME padding); fxn/fyn vanish since gx,gy >= 0
    const float* up = u + base;
    float ucL = __ldg(up + y*512 + x0);
    float ucR = __ldg(up + y*512 + x0 + 1);
    float ulL = (x0 > 0) ? __ldg(up + y*512 + x0 - 1) : 0.f;
    float udL = (y < 511) ? __ldg(up + (y+1)*512 + x0) : 0.f;
    float udR = (y < 511) ? __ldg(up + (y+1)*512 + x0 + 1) : 0.f;

    float oL = ucL + gxL*(ucL - ulL) + gyL*(ucL - udL) + E[1][1] + kL;
    float oR = ucR + gxR*(ucR - ucL) + gyR*(ucR - udR) + E[1][2] + kR;

    *(float2*)&out[idx2] = make_float2(oL, oR);
}

// ---------------- launch ----------------
extern "C" void kernel_launch(void* const* d_in, const int* in_sizes, int n_in,
                              void* d_out, int out_size)
{
    const float* u   = (const float*)d_in[0];
    const float* img = (const float*)d_in[1];
    const float* kx  = (const float*)d_in[2];
    const float* ky  = (const float*)d_in[3];
    const float* dw  = (const float*)d_in[4];
    const float* pw  = (const float*)d_in[5];
    const float* c0k = (const float*)d_in[6];
    const float* c1k = (const float*)d_in[7];
    const float* c2k = (const float*)d_in[8];
    const float* smk = (const float*)d_in[9];
    const float* kap = (const float*)d_in[10];
    float* out = (float*)d_out;

    setup_k<<<1, 128>>>(dw, pw, c2k, c0k, c1k);
    edges_k<<<NPIX/256, 256>>>(img);
    kc_k<<<dim3(16, 16, 8), dim3(8, 32)>>>(u, kap);
    bc0_k<<<(12144*BB + 255)/256, 256>>>(u, c0k);
    bc1_k<<<(8128*BB + 255)/256, 256>>>(c1k);
    bc2_k<<<(6108*BB + 255)/256, 256>>>(kap);
    final_k<<<NPIX/512, 256>>>(u, kx, ky, smk, out);
}

// round 3
// speedup vs baseline: 2.3331x; 1.0663x over previous
#include <cuda_runtime.h>

#define BB 8
#define HH 512
#define WW 512
#define NPIX (BB*HH*WW)

// ---------------- scratch (static device globals; no allocation) ----------------
__device__ __align__(16) float g_c0[8*NPIX];         // band-only valid, [b][ic][y][x]
__device__ __align__(16) float g_c1[8*NPIX];         // band-only valid, [b][oc][y][x]
__device__ __align__(16) float g_kpre[NPIX];         // 8 MB
__device__ float g_DP[72];                           // depthwise∘pointwise folded, [tap][c]
__device__ float g_K2S[72];                          // curve_2 summed over 16 oc, [tap][ic]
__device__ float g_KC[121];                          // composed 11x11 kappa kernel

// zero-padded load from a 512x512 plane
__device__ __forceinline__ float ldz(const float* __restrict__ p, int y, int x) {
    return ((unsigned)y < 512u && (unsigned)x < 512u) ? __ldg(p + y*512 + x) : 0.f;
}

// ---- packed f32x2 helpers (Blackwell FFMA2) ----
typedef unsigned long long u64t;
__device__ __forceinline__ u64t pk2(float lo, float hi) {
    u64t r; asm("mov.b64 %0, {%1, %2};" : "=l"(r) : "f"(lo), "f"(hi)); return r;
}
__device__ __forceinline__ void upk2(u64t v, float& lo, float& hi) {
    asm("mov.b64 {%0, %1}, %2;" : "=f"(lo), "=f"(hi) : "l"(v));
}
__device__ __forceinline__ u64t fma2(u64t a, u64t b, u64t c) {
    u64t d; asm("fma.rn.f32x2 %0, %1, %2, %3;" : "=l"(d) : "l"(a), "l"(b), "l"(c)); return d;
}

// map linear index j to (y,x) inside a boundary band of width Wb
__device__ __forceinline__ void band_coord(int j, int Wb, int& y, int& x) {
    int t1 = Wb * 512;
    if (j < t1)            { y = j / 512;                x = j % 512; }
    else if (j < 2*t1)     { int k = j - t1; y = 512 - Wb + k/512; x = k % 512; }
    else {
        int k = j - 2*t1;
        int h = 512 - 2*Wb;
        int side = k / (h*Wb);
        int m = k % (h*Wb);
        y = Wb + m / Wb;
        int xx = m % Wb;
        x = side ? (512 - Wb + xx) : xx;
    }
}

// ---------------- setup: fold small kernels + compose kappa chain ----------------
__global__ void setup_k(const float* __restrict__ dw,   // (3,3,1,8)
                        const float* __restrict__ pw,   // (1,1,8,8)
                        const float* __restrict__ c2,   // (3,3,8,16)
                        const float* __restrict__ k0,   // (5,5,1,8)
                        const float* __restrict__ k1)   // (5,5,8,8)
{
    __shared__ float sK2S[72];      // [r][ic]
    __shared__ float sK12[49*8];    // [e][ic], 7x7 composed K1∘K2S
    int t = threadIdx.x;
    if (t < 72) {
        int tap = t >> 3, c = t & 7;
        float s = 0.f;
        #pragma unroll
        for (int j = 0; j < 8; j++) s = fmaf(dw[tap*8+j], pw[j*8+c], s);
        g_DP[t] = s;
        float s2 = 0.f;
        #pragma unroll
        for (int oc = 0; oc < 16; oc++) s2 += c2[t*16+oc];
        g_K2S[t] = s2;
        sK2S[t]  = s2;
    }
    __syncthreads();
    for (int i = t; i < 49*8; i += blockDim.x) {
        int e = i >> 3, ic = i & 7;
        int ey = e / 7, ex = e % 7;
        float s = 0.f;
        for (int ry = 0; ry < 3; ry++) {
            int ty = ey - ry; if (ty < 0 || ty > 4) continue;
            for (int rx = 0; rx < 3; rx++) {
                int tx = ex - rx; if (tx < 0 || tx > 4) continue;
                const float* kp = k1 + ((ty*5+tx)*8 + ic)*8;
                const float* rp = sK2S + (ry*3+rx)*8;
                #pragma unroll
                for (int o = 0; o < 8; o++) s = fmaf(kp[o], rp[o], s);
            }
        }
        sK12[i] = s;
    }
    __syncthreads();
    for (int i = t; i < 121; i += blockDim.x) {
        int dy = i / 11, dx = i % 11;
        float s = 0.f;
        for (int sy = 0; sy < 5; sy++) {
            int ey = dy - sy; if (ey < 0 || ey > 6) continue;
            for (int sx = 0; sx < 5; sx++) {
                int ex = dx - sx; if (ex < 0 || ex > 6) continue;
                const float* k0p = k0 + (sy*5+sx)*8;
                const float* k12p = sK12 + (ey*7+ex)*8;
                #pragma unroll
                for (int c = 0; c < 8; c++) s = fmaf(k0p[c], k12p[c], s);
            }
        }
        g_KC[i] = s;
    }
}

// ---------------- kc: composed 11x11 conv of u, times kappa_kernel ----------------
// writes ONLY interior pixels [3,509)^2 (band handled by bc2), so it can run
// concurrently with the band chain.
__global__ __launch_bounds__(256) void kc_k(const float* __restrict__ u,
                                            const float* __restrict__ kap)
{
    __shared__ u64t  sW2[121];      // dup-packed (w,w)
    __shared__ float sIn[42*43];

    int b  = blockIdx.z;
    int x0 = blockIdx.x << 5, y0 = blockIdx.y << 5;
    int tx = threadIdx.x, ty = threadIdx.y;
    int tid = ty * 8 + tx;

    if (tid < 121) { float w = g_KC[tid]; sW2[tid] = pk2(w, w); }

    const float* up = u + b * (HH*WW);
    for (int i = tid; i < 42*42; i += 256) {
        int r = i / 42, c = i % 42;
        sIn[r*43 + c] = ldz(up, y0 + r - 5, x0 + c - 5);
    }
    __syncthreads();

    int bx = tx << 2;
    u64t acc01 = 0ULL, acc23 = 0ULL;
    #pragma unroll 1
    for (int ky = 0; ky < 11; ky++) {
        const float* row = &sIn[(ty + ky)*43 + bx];
        float v[14];
        #pragma unroll
        for (int j = 0; j < 14; j++) v[j] = row[j];
        u64t pp[13];
        #pragma unroll
        for (int j = 0; j < 13; j++) pp[j] = pk2(v[j], v[j+1]);
        const u64t* wr = sW2 + ky*11;
        #pragma unroll
        for (int kx = 0; kx < 11; kx++) {
            u64t w2 = wr[kx];
            acc01 = fma2(pp[kx  ], w2, acc01);
            acc23 = fma2(pp[kx+2], w2, acc23);
        }
    }

    int yy = y0 + ty, xx = x0 + bx;
    if (yy < 3 || yy >= 509) return;
    float a0,a1,a2,a3;
    upk2(acc01, a0, a1);
    upk2(acc23, a2, a3);
    float4 kv = *(const float4*)&kap[yy*512 + xx];
    float r0 = a0*kv.x, r1 = a1*kv.y, r2 = a2*kv.z, r3 = a3*kv.w;
    float* dst = &g_kpre[(b*HH*WW) + yy*512 + xx];
    if (xx >= 4 && xx <= 504) {
        *(float4*)dst = make_float4(r0, r1, r2, r3);
    } else {
        float rv[4] = {r0, r1, r2, r3};
        #pragma unroll
        for (int k = 0; k < 4; k++) {
            int col = xx + k;
            if (col >= 3 && col < 509) dst[k] = rv[k];
        }
    }
}

// ---------------- boundary staged path (band widths 6 / 4 / 3) ----------------
__global__ __launch_bounds__(256) void bc0_k(const float* __restrict__ u,
                                             const float* __restrict__ k0)  // (5,5,1,8)
{
    __shared__ float sW[200];
    for (int i = threadIdx.x; i < 200; i += 256) sW[i] = k0[i];
    __syncthreads();

    const int NB = 2*6*512 + 2*500*6;   // 12144
    int i = blockIdx.x * 256 + threadIdx.x;
    if (i >= NB * BB) return;
    int b = i / NB, j = i % NB;
    int y, x; band_coord(j, 6, y, x);
    const float* up = u + b * (HH*WW);

    float acc[8] = {0,0,0,0,0,0,0,0};
    #pragma unroll
    for (int ky = 0; ky < 5; ky++)
        #pragma unroll
        for (int kx = 0; kx < 5; kx++) {
            float v = ldz(up, y + ky - 2, x + kx - 2);
            int tap = ky*5 + kx;
            #pragma unroll
            for (int oc = 0; oc < 8; oc++) acc[oc] = fmaf(v, sW[tap*8+oc], acc[oc]);
        }
    #pragma unroll
    for (int oc = 0; oc < 8; oc++)
        g_c0[((b*8 + oc)*512 + y)*512 + x] = acc[oc];
}

__global__ __launch_bounds__(256) void bc1_k(const float* __restrict__ k1)  // (5,5,8,8)
{
    __shared__ float sW[1600];
    for (int i = threadIdx.x; i < 1600; i += 256) sW[i] = k1[i];
    __syncthreads();

    const int NB = 2*4*512 + 2*504*4;   // 8128
    int i = blockIdx.x * 256 + threadIdx.x;
    if (i >= NB * BB) return;
    int b = i / NB, j = i % NB;
    int y, x; band_coord(j, 4, y, x);

    float acc[8] = {0,0,0,0,0,0,0,0};
    #pragma unroll 1
    for (int ic = 0; ic < 8; ic++) {
        const float* p = g_c0 + (b*8 + ic)*HH*WW;
        #pragma unroll
        for (int ky = 0; ky < 5; ky++)
            #pragma unroll
            for (int kx = 0; kx < 5; kx++) {
                float v = ldz(p, y + ky - 2, x + kx - 2);
                const float* wp = sW + ((ky*5 + kx)*8 + ic)*8;
                #pragma unroll
                for (int oc = 0; oc < 8; oc++) acc[oc] = fmaf(v, wp[oc], acc[oc]);
            }
    }
    #pragma unroll
    for (int oc = 0; oc < 8; oc++)
        g_c1[((b*8 + oc)*512 + y)*512 + x] = acc[oc];
}

__global__ __launch_bounds__(256) void bc2_k(const float* __restrict__ kap)
{
    __shared__ float sK[72];
    if (threadIdx.x < 72) sK[threadIdx.x] = g_K2S[threadIdx.x];
    __syncthreads();

    const int NB = 2*3*512 + 2*506*3;   // 6108
    int i = blockIdx.x * 256 + threadIdx.x;
    if (i >= NB * BB) return;
    int b = i / NB, j = i % NB;
    int y, x; band_coord(j, 3, y, x);

    float s = 0.f;
    #pragma unroll 1
    for (int ic = 0; ic < 8; ic++) {
        const float* p = g_c1 + (b*8 + ic)*HH*WW;
        #pragma unroll
        for (int ky = 0; ky < 3; ky++)
            #pragma unroll
            for (int kx = 0; kx < 3; kx++) {
                float v = ldz(p, y + ky - 1, x + kx - 1);
                s = fmaf(v, sK[(ky*3 + kx)*8 + ic], s);
            }
    }
    g_kpre[b*HH*WW + y*512 + x] = s * __ldg(kap + y*512 + x);
}

// ---------------- fused final: edges (in smem) + grad (xy-packed) + fd + smoother ----------------
// grid (16,16,8), block (8,32): thread (tx,ty) -> row y0+ty, cols x0+4tx..+3
__global__ __launch_bounds__(256) void final_k(const float* __restrict__ u,
                                               const float* __restrict__ img,
                                               const float* __restrict__ kxw,  // (3,3,1,32)
                                               const float* __restrict__ kyw,  // (3,3,1,32)
                                               const float* __restrict__ smw,  // (5,5,1,1)
                                               float* __restrict__ out)
{
    __shared__ float sImg[36][37];
    __shared__ float sE[34][35];
    __shared__ u64t  sDP2[72];      // dup (w,w)
    __shared__ u64t  sKXY2[288];    // packed (wx, wy)
    __shared__ u64t  sSM2[25];      // dup (w,w)

    int b  = blockIdx.z;
    int x0 = blockIdx.x << 5, y0 = blockIdx.y << 5;
    int tx = threadIdx.x, ty = threadIdx.y;
    int tid = ty * 8 + tx;

    for (int i = tid; i < 288; i += 256) sKXY2[i] = pk2(kxw[i], kyw[i]);
    if (tid < 72) { float w = g_DP[tid]; sDP2[tid] = pk2(w, w); }
    if (tid < 25) { float w = smw[tid]; sSM2[tid] = pk2(w, w); }

    const float* im = img + b * (HH*WW);
    for (int i = tid; i < 36*36; i += 256) {
        int r = i / 36, c = i % 36;
        sImg[r][c] = ldz(im, y0 + r - 2, x0 + c - 2);
    }
    __syncthreads();

    // edges on 34x34 (halo 1), two positions per task packed in fma2
    for (int i = tid; i < 34*17; i += 256) {
        int r = i / 17, c2 = (i % 17) * 2;
        float v0[3][4];
        #pragma unroll
        for (int dy = 0; dy < 3; dy++)
            #pragma unroll
            for (int dx = 0; dx < 4; dx++)
                v0[dy][dx] = sImg[r+dy][c2+dx];
        u64t acc[8] = {0,0,0,0,0,0,0,0};
        #pragma unroll
        for (int t = 0; t < 9; t++) {
            int dy = t / 3, dx = t % 3;
            u64t p = pk2(v0[dy][dx], v0[dy][dx+1]);
            #pragma unroll
            for (int ch = 0; ch < 8; ch++) acc[ch] = fma2(p, sDP2[t*8+ch], acc[ch]);
        }
        float sA = 0.f, sB = 0.f;
        #pragma unroll
        for (int ch = 0; ch < 8; ch++) {
            float a, bb; upk2(acc[ch], a, bb);
            sA += fmaxf(a, 0.f); sB += fmaxf(bb, 0.f);
        }
        int gy = y0 + r - 1;
        int gx0 = x0 + c2 - 1, gx1 = gx0 + 1;
        bool yok = (unsigned)gy < 512u;
        sE[r][c2]   = (yok && (unsigned)gx0 < 512u) ? __fdividef(sA, 1.f + fabsf(sA)) : 0.f;
        sE[r][c2+1] = (yok && (unsigned)gx1 < 512u) ? __fdividef(sB, 1.f + fabsf(sB)) : 0.f;
    }
    __syncthreads();

    int xb = x0 + (tx << 2);
    int y  = y0 + ty;
    int base = b * (HH*WW);

    // edges neighborhood and dup-packed taps
    float E[3][6];
    #pragma unroll
    for (int dy = 0; dy < 3; dy++)
        #pragma unroll
        for (int j = 0; j < 6; j++)
            E[dy][j] = sE[ty+dy][(tx<<2)+j];

    u64t D[18];
    #pragma unroll
    for (int dy = 0; dy < 3; dy++)
        #pragma unroll
        for (int j = 0; j < 6; j++)
            D[dy*6 + j] = pk2(E[dy][j], E[dy][j]);

    // grad: per channel, per tap: one packed (wx,wy) weight, 4 pixels
    float gx[4] = {0,0,0,0}, gy[4] = {0,0,0,0};
    #pragma unroll 2
    for (int c = 0; c < 32; c++) {
        u64t s0 = 0ULL, s1 = 0ULL, s2 = 0ULL, s3 = 0ULL;
        #pragma unroll
        for (int t = 0; t < 9; t++) {
            int dy = t / 3, dx = t % 3;
            u64t w2 = sKXY2[t*32 + c];
            s0 = fma2(D[dy*6+dx  ], w2, s0);
            s1 = fma2(D[dy*6+dx+1], w2, s1);
            s2 = fma2(D[dy*6+dx+2], w2, s2);
            s3 = fma2(D[dy*6+dx+3], w2, s3);
        }
        float a, bb;
        upk2(s0, a, bb); gx[0] += fmaxf(a,0.f); gy[0] += fmaxf(bb,0.f);
        upk2(s1, a, bb); gx[1] += fmaxf(a,0.f); gy[1] += fmaxf(bb,0.f);
        upk2(s2, a, bb); gx[2] += fmaxf(a,0.f); gy[2] += fmaxf(bb,0.f);
        upk2(s3, a, bb); gx[3] += fmaxf(a,0.f); gy[3] += fmaxf(bb,0.f);
    }

    // smoother: conv5x5 of g_kpre, pixel-pair packed (A = px0,1; B = px2,3)
    const float* kp = g_kpre + base;
    u64t kaccA = 0ULL, kaccB = 0ULL;
    #pragma unroll
    for (int dy = 0; dy < 5; dy++) {
        float P[8];
        #pragma unroll
        for (int dx = 0; dx < 8; dx++) P[dx] = ldz(kp, y + dy - 2, xb + dx - 2);
        u64t pp[7];
        #pragma unroll
        for (int j = 0; j < 7; j++) pp[j] = pk2(P[j], P[j+1]);
        #pragma unroll
        for (int dx = 0; dx < 5; dx++) {
            u64t w2 = sSM2[dy*5 + dx];
            kaccA = fma2(pp[dx  ], w2, kaccA);
            kaccB = fma2(pp[dx+2], w2, kaccB);
        }
    }
    float ka[4];
    upk2(kaccA, ka[0], ka[1]);
    upk2(kaccB, ka[2], ka[3]);

    // finite differences; fxn/fyn vanish since gx,gy >= 0
    const float* up = u + base;
    float4 uc4 = *(const float4*)&up[y*512 + xb];
    float uc[4] = {uc4.x, uc4.y, uc4.z, uc4.w};
    float ul0 = (xb > 0) ? __ldg(&up[y*512 + xb - 1]) : 0.f;
    float ul[4] = {ul0, uc[0], uc[1], uc[2]};
    float ud[4];
    if (y < 511) {
        float4 d4 = *(const float4*)&up[(y+1)*512 + xb];
        ud[0] = d4.x; ud[1] = d4.y; ud[2] = d4.z; ud[3] = d4.w;
    } else {
        ud[0] = ud[1] = ud[2] = ud[3] = 0.f;
    }

    float o[4];
    #pragma unroll
    for (int k = 0; k < 4; k++)
        o[k] = uc[k] + gx[k]*(uc[k]-ul[k]) + gy[k]*(uc[k]-ud[k]) + E[1][k+1] + ka[k];

    *(float4*)&out[base + y*512 + xb] = make_float4(o[0], o[1], o[2], o[3]);
}

// ---------------- launch (fork/join for parallel band chain) ----------------
extern "C" void kernel_launch(void* const* d_in, const int* in_sizes, int n_in,
                              void* d_out, int out_size)
{
    const float* u   = (const float*)d_in[0];
    const float* img = (const float*)d_in[1];
    const float* kx  = (const float*)d_in[2];
    const float* ky  = (const float*)d_in[3];
    const float* dw  = (const float*)d_in[4];
    const float* pw  = (const float*)d_in[5];
    const float* c0k = (const float*)d_in[6];
    const float* c1k = (const float*)d_in[7];
    const float* c2k = (const float*)d_in[8];
    const float* smk = (const float*)d_in[9];
    const float* kap = (const float*)d_in[10];
    float* out = (float*)d_out;

    static cudaStream_t side = nullptr;
    static cudaEvent_t evF = nullptr, evS = nullptr, evJ = nullptr;
    if (!side) {
        cudaStreamCreateWithFlags(&side, cudaStreamNonBlocking);
        cudaEventCreateWithFlags(&evF, cudaEventDisableTiming);
        cudaEventCreateWithFlags(&evS, cudaEventDisableTiming);
        cudaEventCreateWithFlags(&evJ, cudaEventDisableTiming);
    }

    // fork at start: bc0/bc1 depend only on inputs
    cudaEventRecord(evF, 0);
    cudaStreamWaitEvent(side, evF, 0);
    bc0_k<<<(12144*BB + 255)/256, 256, 0, side>>>(u, c0k);
    bc1_k<<<(8128*BB + 255)/256, 256, 0, side>>>(c1k);

    // main: setup, then kc (interior kappa)
    setup_k<<<1, 128>>>(dw, pw, c2k, c0k, c1k);
    cudaEventRecord(evS, 0);
    cudaStreamWaitEvent(side, evS, 0);      // bc2 needs g_K2S from setup
    bc2_k<<<(6108*BB + 255)/256, 256, 0, side>>>(kap);
    cudaEventRecord(evJ, side);

    kc_k<<<dim3(16, 16, 8), dim3(8, 32)>>>(u, kap);

    // join: final needs kpre (kc + bc2)
    cudaStreamWaitEvent(0, evJ, 0);
    final_k<<<dim3(16, 16, 8), dim3(8, 32)>>>(u, img, kx, ky, smk, out);
}

// round 4
// speedup vs baseline: 2.5251x; 1.0823x over previous
#include <cuda_runtime.h>

#define BB 8
#define HH 512
#define WW 512
#define NPIX (BB*HH*WW)

// ---------------- scratch (static device globals; no allocation) ----------------
__device__ __align__(16) float g_kpre[NPIX];         // 8 MB
__device__ float g_DP[72];                           // depthwise∘pointwise folded, [tap][c]
__device__ float g_KC[121];                          // composed 11x11 kappa kernel

// zero-padded load from a 512x512 plane
__device__ __forceinline__ float ldz(const float* __restrict__ p, int y, int x) {
    return ((unsigned)y < 512u && (unsigned)x < 512u) ? __ldg(p + y*512 + x) : 0.f;
}

// ---- packed f32x2 helpers (Blackwell FFMA2) ----
typedef unsigned long long u64t;
__device__ __forceinline__ u64t pk2(float lo, float hi) {
    u64t r; asm("mov.b64 %0, {%1, %2};" : "=l"(r) : "f"(lo), "f"(hi)); return r;
}
__device__ __forceinline__ void upk2(u64t v, float& lo, float& hi) {
    asm("mov.b64 {%0, %1}, %2;" : "=f"(lo), "=f"(hi) : "l"(v));
}
__device__ __forceinline__ u64t fma2(u64t a, u64t b, u64t c) {
    u64t d; asm("fma.rn.f32x2 %0, %1, %2, %3;" : "=l"(d) : "l"(a), "l"(b), "l"(c)); return d;
}

// ---------------- setup: fold DP + compose kappa chain into 11x11 ----------------
__global__ void setup_k(const float* __restrict__ dw,   // (3,3,1,8)
                        const float* __restrict__ pw,   // (1,1,8,8)
                        const float* __restrict__ c2,   // (3,3,8,16)
                        const float* __restrict__ k0,   // (5,5,1,8)
                        const float* __restrict__ k1)   // (5,5,8,8)
{
    __shared__ float sK2S[72];      // [r][ic]
    __shared__ float sK12[49*8];    // [e][ic], 7x7 composed K1∘K2S
    int t = threadIdx.x;
    if (t < 72) {
        int tap = t >> 3, c = t & 7;
        float s = 0.f;
        #pragma unroll
        for (int j = 0; j < 8; j++) s = fmaf(dw[tap*8+j], pw[j*8+c], s);
        g_DP[t] = s;
        float s2 = 0.f;
        #pragma unroll
        for (int oc = 0; oc < 16; oc++) s2 += c2[t*16+oc];
        sK2S[t]  = s2;
    }
    __syncthreads();
    for (int i = t; i < 49*8; i += blockDim.x) {
        int e = i >> 3, ic = i & 7;
        int ey = e / 7, ex = e % 7;
        float s = 0.f;
        for (int ry = 0; ry < 3; ry++) {
            int ty = ey - ry; if (ty < 0 || ty > 4) continue;
            for (int rx = 0; rx < 3; rx++) {
                int tx = ex - rx; if (tx < 0 || tx > 4) continue;
                const float* kp = k1 + ((ty*5+tx)*8 + ic)*8;
                const float* rp = sK2S + (ry*3+rx)*8;
                #pragma unroll
                for (int o = 0; o < 8; o++) s = fmaf(kp[o], rp[o], s);
            }
        }
        sK12[i] = s;
    }
    __syncthreads();
    for (int i = t; i < 121; i += blockDim.x) {
        int dy = i / 11, dx = i % 11;
        float s = 0.f;
        for (int sy = 0; sy < 5; sy++) {
            int ey = dy - sy; if (ey < 0 || ey > 6) continue;
            for (int sx = 0; sx < 5; sx++) {
                int ex = dx - sx; if (ex < 0 || ex > 6) continue;
                const float* k0p = k0 + (sy*5+sx)*8;
                const float* k12p = sK12 + (ey*7+ex)*8;
                #pragma unroll
                for (int c = 0; c < 8; c++) s = fmaf(k0p[c], k12p[c], s);
            }
        }
        g_KC[i] = s;
    }
}

// ---------------- kc: composed 11x11 conv of u, times kappa_kernel (interior only) ----------------
__global__ __launch_bounds__(256) void kc_k(const float* __restrict__ u,
                                            const float* __restrict__ kap)
{
    __shared__ u64t  sW2[121];      // dup-packed (w,w)
    __shared__ float sIn[42*43];

    int b  = blockIdx.z;
    int x0 = blockIdx.x << 5, y0 = blockIdx.y << 5;
    int tx = threadIdx.x, ty = threadIdx.y;
    int tid = ty * 8 + tx;

    if (tid < 121) { float w = g_KC[tid]; sW2[tid] = pk2(w, w); }

    const float* up = u + b * (HH*WW);
    for (int i = tid; i < 42*42; i += 256) {
        int r = i / 42, c = i % 42;
        sIn[r*43 + c] = ldz(up, y0 + r - 5, x0 + c - 5);
    }
    __syncthreads();

    int bx = tx << 2;
    u64t acc01 = 0ULL, acc23 = 0ULL;
    #pragma unroll 1
    for (int ky = 0; ky < 11; ky++) {
        const float* row = &sIn[(ty + ky)*43 + bx];
        float v[14];
        #pragma unroll
        for (int j = 0; j < 14; j++) v[j] = row[j];
        u64t pp[13];
        #pragma unroll
        for (int j = 0; j < 13; j++) pp[j] = pk2(v[j], v[j+1]);
        const u64t* wr = sW2 + ky*11;
        #pragma unroll
        for (int kx = 0; kx < 11; kx++) {
            u64t w2 = wr[kx];
            acc01 = fma2(pp[kx  ], w2, acc01);
            acc23 = fma2(pp[kx+2], w2, acc23);
        }
    }

    int yy = y0 + ty, xx = x0 + bx;
    if (yy < 3 || yy >= 509) return;
    float a0,a1,a2,a3;
    upk2(acc01, a0, a1);
    upk2(acc23, a2, a3);
    float4 kv = *(const float4*)&kap[yy*512 + xx];
    float r0 = a0*kv.x, r1 = a1*kv.y, r2 = a2*kv.z, r3 = a3*kv.w;
    float* dst = &g_kpre[(b*HH*WW) + yy*512 + xx];
    if (xx >= 4 && xx <= 504) {
        *(float4*)dst = make_float4(r0, r1, r2, r3);
    } else {
        float rv[4] = {r0, r1, r2, r3};
        #pragma unroll
        for (int k = 0; k < 4; k++) {
            int col = xx + k;
            if (col >= 3 && col < 509) dst[k] = rv[k];
        }
    }
}

// ---------------- boundary: full staged band chain in ONE kernel, smem only ----------------
// 32 segments x 8 batches. Sides: 0=top rows 0..2 (full width), 1=bottom rows 509..511,
// 2=left cols 0..2 rows [3,509), 3=right cols 509..511 rows [3,509).
// Orientation handled by permuting conv-tap order at weight-load time.
__global__ __launch_bounds__(256) void boundary_k(
    const float* __restrict__ u,
    const float* __restrict__ k0,   // (5,5,1,8)
    const float* __restrict__ k1,   // (5,5,8,8)
    const float* __restrict__ c2,   // (3,3,8,16)
    const float* __restrict__ kap)
{
    __shared__ float sU[8][76];
    __shared__ u64t  sW0[25][4];       // [band_tap*5+along_tap][oc-pair]
    __shared__ u64t  sW1[200][4];      // [(tb*5+ta)*8+ic][oc-pair]
    __shared__ float sK2S[9][8];       // [tb*3+ta][ic]
    __shared__ float sC0[8][6][72];    // [ch][band][along]  (along tile offset +2)
    __shared__ float sC1[8][4][68];    // [ch][band][along]  (along tile offset +4)

    int tid = threadIdx.x;
    int b   = blockIdx.y;
    int seg = blockIdx.x;                 // 0..31
    int side = seg >> 3, s = seg & 7;
    bool bandIsX = (side >= 2);
    bool hi = (side & 1);                 // bottom / right
    int band_base  = hi ? 504 : 0;        // u-tile band origin
    int g0c = hi ? 506 : 0;               // c0 band origin (6 positions)
    int g1  = hi ? 508 : 0;               // c1 band origin (4 positions)
    int g2  = hi ? 509 : 0;               // output band origin (3 positions)
    int along_base = bandIsX ? (s*64 - 2) : (s*64 - 5);

    // ---- weights, permuted to [band][along] tap order ----
    for (int i = tid; i < 25; i += 256) {
        int ky = i / 5, kx = i % 5;
        int tb = bandIsX ? kx : ky, ta = bandIsX ? ky : kx;
        const float* p = k0 + i*8;
        #pragma unroll
        for (int j = 0; j < 4; j++) sW0[tb*5+ta][j] = pk2(p[2*j], p[2*j+1]);
    }
    for (int i = tid; i < 200; i += 256) {
        int tap = i >> 3, ic = i & 7;
        int ky = tap / 5, kx = tap % 5;
        int tb = bandIsX ? kx : ky, ta = bandIsX ? ky : kx;
        const float* p = k1 + i*8;
        #pragma unroll
        for (int j = 0; j < 4; j++) sW1[(tb*5+ta)*8+ic][j] = pk2(p[2*j], p[2*j+1]);
    }
    for (int i = tid; i < 72; i += 256) {
        int tap = i >> 3, ic = i & 7;
        int ry = tap / 3, rx = tap % 3;
        int tb = bandIsX ? rx : ry, ta = bandIsX ? ry : rx;
        float ssum = 0.f;
        #pragma unroll
        for (int oc = 0; oc < 16; oc++) ssum += c2[i*16 + oc];
        sK2S[tb*3+ta][ic] = ssum;
    }

    // ---- u tile (zero-padded) ----
    const float* up = u + b*(HH*WW);
    for (int i = tid; i < 8*74; i += 256) {
        int bp = i / 74, a = i % 74;
        int gb = band_base + bp, ga = along_base + a;
        int y = bandIsX ? ga : gb, x = bandIsX ? gb : ga;
        sU[bp][a] = ((unsigned)y < 512u && (unsigned)x < 512u) ? up[y*512+x] : 0.f;
    }
    __syncthreads();

    // ---- stage c0: 6 band x 70 along, 8 channels ----
    for (int i = tid; i < 420; i += 256) {
        int bp = i / 70, j = i % 70;
        int a = j + 2;
        int ga = along_base + a;
        u64t acc[4] = {0,0,0,0};
        if ((unsigned)ga < 512u) {          // out-of-grid conv outputs are ZERO (SAME pad)
            #pragma unroll
            for (int kb = 0; kb < 5; kb++) {
                int bu = g0c + bp + kb - 2 - band_base;
                if ((unsigned)bu < 8u) {
                    #pragma unroll
                    for (int ka = 0; ka < 5; ka++) {
                        float v = sU[bu][a + ka - 2];
                        u64t v2 = pk2(v, v);
                        const u64t* w = sW0[kb*5+ka];
                        acc[0]=fma2(v2,w[0],acc[0]); acc[1]=fma2(v2,w[1],acc[1]);
                        acc[2]=fma2(v2,w[2],acc[2]); acc[3]=fma2(v2,w[3],acc[3]);
                    }
                }
            }
        }
        #pragma unroll
        for (int q = 0; q < 4; q++) {
            float lo, hh; upk2(acc[q], lo, hh);
            sC0[2*q][bp][j] = lo; sC0[2*q+1][bp][j] = hh;
        }
    }
    __syncthreads();

    // ---- stage c1: 4 band x 66 along, 8->8 channels ----
    for (int i = tid; i < 264; i += 256) {
        int bp = i / 66, j = i % 66;
        int a = j + 4;
        int ga = along_base + a;
        u64t acc[4] = {0,0,0,0};
        if ((unsigned)ga < 512u) {
            #pragma unroll
            for (int kb = 0; kb < 5; kb++) {
                int i0 = g1 + bp + kb - 2 - g0c;
                if ((unsigned)i0 < 6u) {
                    #pragma unroll
                    for (int ka = 0; ka < 5; ka++) {
                        int col = a + ka - 4;
                        const u64t* w = &sW1[(kb*5+ka)*8][0];
                        #pragma unroll
                        for (int ic = 0; ic < 8; ic++) {
                            float v = sC0[ic][i0][col];
                            u64t v2 = pk2(v, v);
                            const u64t* wi = w + ic*4;
                            acc[0]=fma2(v2,wi[0],acc[0]); acc[1]=fma2(v2,wi[1],acc[1]);
                            acc[2]=fma2(v2,wi[2],acc[2]); acc[3]=fma2(v2,wi[3],acc[3]);
                        }
                    }
                }
            }
        }
        #pragma unroll
        for (int q = 0; q < 4; q++) {
            float lo, hh; upk2(acc[q], lo, hh);
            sC1[2*q][bp][j] = lo; sC1[2*q+1][bp][j] = hh;
        }
    }
    __syncthreads();

    // ---- stage c2 + kappa_kernel multiply + write band of g_kpre ----
    float* kpre = g_kpre + b*(HH*WW);
    for (int i = tid; i < 192; i += 256) {
        int bp = i / 64, j = i % 64;
        int a = j + 5;
        int ga = along_base + a;
        int gb = g2 + bp;
        if (bandIsX && (ga < 3 || ga >= 509)) continue;   // those cells owned by top/bottom
        float ssum = 0.f;
        #pragma unroll
        for (int kb = 0; kb < 3; kb++) {
            int i1 = gb + kb - 1 - g1;
            if ((unsigned)i1 < 4u) {
                #pragma unroll
                for (int ka = 0; ka < 3; ka++) {
                    int col = a + ka - 5;
                    #pragma unroll
                    for (int ic = 0; ic < 8; ic++)
                        ssum = fmaf(sC1[ic][i1][col], sK2S[kb*3+ka][ic], ssum);
                }
            }
        }
        int y = bandIsX ? ga : gb, x = bandIsX ? gb : ga;
        kpre[y*512+x] = ssum * __ldg(kap + y*512 + x);
    }
}

// ---------------- fused final: edges (in smem) + grad (xy-packed) + fd + smoother ----------------
__global__ __launch_bounds__(256) void final_k(const float* __restrict__ u,
                                               const float* __restrict__ img,
                                               const float* __restrict__ kxw,  // (3,3,1,32)
                                               const float* __restrict__ kyw,  // (3,3,1,32)
                                               const float* __restrict__ smw,  // (5,5,1,1)
                                               float* __restrict__ out)
{
    __shared__ float sImg[36][37];
    __shared__ float sE[34][35];
    __shared__ u64t  sDP2[72];      // dup (w,w)
    __shared__ u64t  sKXY2[288];    // packed (wx, wy)
    __shared__ u64t  sSM2[25];      // dup (w,w)

    int b  = blockIdx.z;
    int x0 = blockIdx.x << 5, y0 = blockIdx.y << 5;
    int tx = threadIdx.x, ty = threadIdx.y;
    int tid = ty * 8 + tx;

    for (int i = tid; i < 288; i += 256) sKXY2[i] = pk2(kxw[i], kyw[i]);
    if (tid < 72) { float w = g_DP[tid]; sDP2[tid] = pk2(w, w); }
    if (tid < 25) { float w = smw[tid]; sSM2[tid] = pk2(w, w); }

    const float* im = img + b * (HH*WW);
    for (int i = tid; i < 36*36; i += 256) {
        int r = i / 36, c = i % 36;
        sImg[r][c] = ldz(im, y0 + r - 2, x0 + c - 2);
    }
    __syncthreads();

    // edges on 34x34 (halo 1), two positions per task packed in fma2
    for (int i = tid; i < 34*17; i += 256) {
        int r = i / 17, c2 = (i % 17) * 2;
        float v0[3][4];
        #pragma unroll
        for (int dy = 0; dy < 3; dy++)
            #pragma unroll
            for (int dx = 0; dx < 4; dx++)
                v0[dy][dx] = sImg[r+dy][c2+dx];
        u64t acc[8] = {0,0,0,0,0,0,0,0};
        #pragma unroll
        for (int t = 0; t < 9; t++) {
            int dy = t / 3, dx = t % 3;
            u64t p = pk2(v0[dy][dx], v0[dy][dx+1]);
            #pragma unroll
            for (int ch = 0; ch < 8; ch++) acc[ch] = fma2(p, sDP2[t*8+ch], acc[ch]);
        }
        float sA = 0.f, sB = 0.f;
        #pragma unroll
        for (int ch = 0; ch < 8; ch++) {
            float a, bb; upk2(acc[ch], a, bb);
            sA += fmaxf(a, 0.f); sB += fmaxf(bb, 0.f);
        }
        int gy = y0 + r - 1;
        int gx0 = x0 + c2 - 1, gx1 = gx0 + 1;
        bool yok = (unsigned)gy < 512u;
        sE[r][c2]   = (yok && (unsigned)gx0 < 512u) ? __fdividef(sA, 1.f + fabsf(sA)) : 0.f;
        sE[r][c2+1] = (yok && (unsigned)gx1 < 512u) ? __fdividef(sB, 1.f + fabsf(sB)) : 0.f;
    }
    __syncthreads();

    int xb = x0 + (tx << 2);
    int y  = y0 + ty;
    int base = b * (HH*WW);

    float E[3][6];
    #pragma unroll
    for (int dy = 0; dy < 3; dy++)
        #pragma unroll
        for (int j = 0; j < 6; j++)
            E[dy][j] = sE[ty+dy][(tx<<2)+j];

    u64t D[18];
    #pragma unroll
    for (int dy = 0; dy < 3; dy++)
        #pragma unroll
        for (int j = 0; j < 6; j++)
            D[dy*6 + j] = pk2(E[dy][j], E[dy][j]);

    float gx[4] = {0,0,0,0}, gy[4] = {0,0,0,0};
    #pragma unroll 2
    for (int c = 0; c < 32; c++) {
        u64t s0 = 0ULL, s1 = 0ULL, s2 = 0ULL, s3 = 0ULL;
        #pragma unroll
        for (int t = 0; t < 9; t++) {
            int dy = t / 3, dx = t % 3;
            u64t w2 = sKXY2[t*32 + c];
            s0 = fma2(D[dy*6+dx  ], w2, s0);
            s1 = fma2(D[dy*6+dx+1], w2, s1);
            s2 = fma2(D[dy*6+dx+2], w2, s2);
            s3 = fma2(D[dy*6+dx+3], w2, s3);
        }
        float a, bb;
        upk2(s0, a, bb); gx[0] += fmaxf(a,0.f); gy[0] += fmaxf(bb,0.f);
        upk2(s1, a, bb); gx[1] += fmaxf(a,0.f); gy[1] += fmaxf(bb,0.f);
        upk2(s2, a, bb); gx[2] += fmaxf(a,0.f); gy[2] += fmaxf(bb,0.f);
        upk2(s3, a, bb); gx[3] += fmaxf(a,0.f); gy[3] += fmaxf(bb,0.f);
    }

    // smoother: conv5x5 of g_kpre, pixel-pair packed
    const float* kp = g_kpre + base;
    u64t kaccA = 0ULL, kaccB = 0ULL;
    #pragma unroll
    for (int dy = 0; dy < 5; dy++) {
        float P[8];
        #pragma unroll
        for (int dx = 0; dx < 8; dx++) P[dx] = ldz(kp, y + dy - 2, xb + dx - 2);
        u64t pp[7];
        #pragma unroll
        for (int j = 0; j < 7; j++) pp[j] = pk2(P[j], P[j+1]);
        #pragma unroll
        for (int dx = 0; dx < 5; dx++) {
            u64t w2 = sSM2[dy*5 + dx];
            kaccA = fma2(pp[dx  ], w2, kaccA);
            kaccB = fma2(pp[dx+2], w2, kaccB);
        }
    }
    float ka[4];
    upk2(kaccA, ka[0], ka[1]);
    upk2(kaccB, ka[2], ka[3]);

    // finite differences; fxn/fyn vanish since gx,gy >= 0
    const float* up = u + base;
    float4 uc4 = *(const float4*)&up[y*512 + xb];
    float uc[4] = {uc4.x, uc4.y, uc4.z, uc4.w};
    float ul0 = (xb > 0) ? __ldg(&up[y*512 + xb - 1]) : 0.f;
    float ul[4] = {ul0, uc[0], uc[1], uc[2]};
    float ud[4];
    if (y < 511) {
        float4 d4 = *(const float4*)&up[(y+1)*512 + xb];
        ud[0] = d4.x; ud[1] = d4.y; ud[2] = d4.z; ud[3] = d4.w;
    } else {
        ud[0] = ud[1] = ud[2] = ud[3] = 0.f;
    }

    float o[4];
    #pragma unroll
    for (int k = 0; k < 4; k++)
        o[k] = uc[k] + gx[k]*(uc[k]-ul[k]) + gy[k]*(uc[k]-ud[k]) + E[1][k+1] + ka[k];

    *(float4*)&out[base + y*512 + xb] = make_float4(o[0], o[1], o[2], o[3]);
}

// ---------------- launch ----------------
extern "C" void kernel_launch(void* const* d_in, const int* in_sizes, int n_in,
                              void* d_out, int out_size)
{
    const float* u   = (const float*)d_in[0];
    const float* img = (const float*)d_in[1];
    const float* kx  = (const float*)d_in[2];
    const float* ky  = (const float*)d_in[3];
    const float* dw  = (const float*)d_in[4];
    const float* pw  = (const float*)d_in[5];
    const float* c0k = (const float*)d_in[6];
    const float* c1k = (const float*)d_in[7];
    const float* c2k = (const float*)d_in[8];
    const float* smk = (const float*)d_in[9];
    const float* kap = (const float*)d_in[10];
    float* out = (float*)d_out;

    static cudaStream_t side = nullptr;
    static cudaEvent_t evF = nullptr, evJ = nullptr;
    if (!side) {
        cudaStreamCreateWithFlags(&side, cudaStreamNonBlocking);
        cudaEventCreateWithFlags(&evF, cudaEventDisableTiming);
        cudaEventCreateWithFlags(&evJ, cudaEventDisableTiming);
    }

    // fork at start: boundary depends only on inputs (computes its own K2S)
    cudaEventRecord(evF, 0);
    cudaStreamWaitEvent(side, evF, 0);
    boundary_k<<<dim3(32, BB), 256, 0, side>>>(u, c0k, c1k, c2k, kap);
    cudaEventRecord(evJ, side);

    // main: setup -> kc (interior kappa); boundary hides underneath
    setup_k<<<1, 128>>>(dw, pw, c2k, c0k, c1k);
    kc_k<<<dim3(16, 16, 8), dim3(8, 32)>>>(u, kap);

    // join: final needs full g_kpre (kc interior + boundary band)
    cudaStreamWaitEvent(0, evJ, 0);
    final_k<<<dim3(16, 16, 8), dim3(8, 32)>>>(u, img, kx, ky, smk, out);
}

// round 7
// speedup vs baseline: 2.5680x; 1.0170x over previous
#include <cuda_runtime.h>

#define BB 8
#define HH 512
#define WW 512
#define NPIX (BB*HH*WW)

// ---------------- scratch (static device globals; no allocation) ----------------
__device__ __align__(16) float g_kpre[NPIX];         // 8 MB
__device__ float g_DP[72];                           // depthwise∘pointwise folded, [tap][c]
__device__ float g_KC[121];                          // composed 11x11 kappa kernel

// zero-padded load from a 512x512 plane
__device__ __forceinline__ float ldz(const float* __restrict__ p, int y, int x) {
    return ((unsigned)y < 512u && (unsigned)x < 512u) ? __ldg(p + y*512 + x) : 0.f;
}

// ---- packed f32x2 helpers (Blackwell FFMA2) ----
typedef unsigned long long u64t;
__device__ __forceinline__ u64t pk2(float lo, float hi) {
    u64t r; asm("mov.b64 %0, {%1, %2};" : "=l"(r) : "f"(lo), "f"(hi)); return r;
}
__device__ __forceinline__ void upk2(u64t v, float& lo, float& hi) {
    asm("mov.b64 {%0, %1}, %2;" : "=f"(lo), "=f"(hi) : "l"(v));
}
__device__ __forceinline__ u64t fma2(u64t a, u64t b, u64t c) {
    u64t d; asm("fma.rn.f32x2 %0, %1, %2, %3;" : "=l"(d) : "l"(a), "l"(b), "l"(c)); return d;
}

// ---------------- setup: fold DP + compose kappa chain into 11x11 ----------------
__global__ void setup_k(const float* __restrict__ dw,   // (3,3,1,8)
                        const float* __restrict__ pw,   // (1,1,8,8)
                        const float* __restrict__ c2,   // (3,3,8,16)
                        const float* __restrict__ k0,   // (5,5,1,8)
                        const float* __restrict__ k1)   // (5,5,8,8)
{
    __shared__ float sK2S[72];
    __shared__ float sK12[49*8];
    int t = threadIdx.x;
    if (t < 72) {
        int tap = t >> 3, c = t & 7;
        float s = 0.f;
        #pragma unroll
        for (int j = 0; j < 8; j++) s = fmaf(dw[tap*8+j], pw[j*8+c], s);
        g_DP[t] = s;
        float s2 = 0.f;
        #pragma unroll
        for (int oc = 0; oc < 16; oc++) s2 += c2[t*16+oc];
        sK2S[t]  = s2;
    }
    __syncthreads();
    for (int i = t; i < 49*8; i += blockDim.x) {
        int e = i >> 3, ic = i & 7;
        int ey = e / 7, ex = e % 7;
        float s = 0.f;
        for (int ry = 0; ry < 3; ry++) {
            int ty = ey - ry; if (ty < 0 || ty > 4) continue;
            for (int rx = 0; rx < 3; rx++) {
                int tx = ex - rx; if (tx < 0 || tx > 4) continue;
                const float* kp = k1 + ((ty*5+tx)*8 + ic)*8;
                const float* rp = sK2S + (ry*3+rx)*8;
                #pragma unroll
                for (int o = 0; o < 8; o++) s = fmaf(kp[o], rp[o], s);
            }
        }
        sK12[i] = s;
    }
    __syncthreads();
    for (int i = t; i < 121; i += blockDim.x) {
        int dy = i / 11, dx = i % 11;
        float s = 0.f;
        for (int sy = 0; sy < 5; sy++) {
            int ey = dy - sy; if (ey < 0 || ey > 6) continue;
            for (int sx = 0; sx < 5; sx++) {
                int ex = dx - sx; if (ex < 0 || ex > 6) continue;
                const float* k0p = k0 + (sy*5+sx)*8;
                const float* k12p = sK12 + (ey*7+ex)*8;
                #pragma unroll
                for (int c = 0; c < 8; c++) s = fmaf(k0p[c], k12p[c], s);
            }
        }
        g_KC[i] = s;
    }
}

// ---------------- kc: composed 11x11 conv of u, times kappa_kernel (interior only) ----------------
__global__ __launch_bounds__(256) void kc_k(const float* __restrict__ u,
                                            const float* __restrict__ kap)
{
    __shared__ u64t  sW2[121];
    __shared__ float sIn[42*43];

    int b  = blockIdx.z;
    int x0 = blockIdx.x << 5, y0 = blockIdx.y << 5;
    int tx = threadIdx.x, ty = threadIdx.y;
    int tid = ty * 8 + tx;

    if (tid < 121) { float w = g_KC[tid]; sW2[tid] = pk2(w, w); }

    const float* up = u + b * (HH*WW);
    for (int i = tid; i < 42*42; i += 256) {
        int r = i / 42, c = i % 42;
        sIn[r*43 + c] = ldz(up, y0 + r - 5, x0 + c - 5);
    }
    __syncthreads();

    int bx = tx << 2;
    u64t acc01 = 0ULL, acc23 = 0ULL;
    #pragma unroll 1
    for (int ky = 0; ky < 11; ky++) {
        const float* row = &sIn[(ty + ky)*43 + bx];
        float v[14];
        #pragma unroll
        for (int j = 0; j < 14; j++) v[j] = row[j];
        u64t pp[13];
        #pragma unroll
        for (int j = 0; j < 13; j++) pp[j] = pk2(v[j], v[j+1]);
        const u64t* wr = sW2 + ky*11;
        #pragma unroll
        for (int kx = 0; kx < 11; kx++) {
            u64t w2 = wr[kx];
            acc01 = fma2(pp[kx  ], w2, acc01);
            acc23 = fma2(pp[kx+2], w2, acc23);
        }
    }

    int yy = y0 + ty, xx = x0 + bx;
    if (yy < 3 || yy >= 509) return;
    float a0,a1,a2,a3;
    upk2(acc01, a0, a1);
    upk2(acc23, a2, a3);
    float4 kv = *(const float4*)&kap[yy*512 + xx];
    float r0 = a0*kv.x, r1 = a1*kv.y, r2 = a2*kv.z, r3 = a3*kv.w;
    float* dst = &g_kpre[(b*HH*WW) + yy*512 + xx];
    if (xx >= 4 && xx <= 504) {
        *(float4*)dst = make_float4(r0, r1, r2, r3);
    } else {
        float rv[4] = {r0, r1, r2, r3};
        #pragma unroll
        for (int k = 0; k < 4; k++) {
            int col = xx + k;
            if (col >= 3 && col < 509) dst[k] = rv[k];
        }
    }
}

// ---------------- boundary: full staged band chain in ONE kernel, smem only ----------------
__global__ __launch_bounds__(256) void boundary_k(
    const float* __restrict__ u,
    const float* __restrict__ k0,   // (5,5,1,8)
    const float* __restrict__ k1,   // (5,5,8,8)
    const float* __restrict__ c2,   // (3,3,8,16)
    const float* __restrict__ kap)
{
    __shared__ float sU[8][76];
    __shared__ u64t  sW0[25][4];
    __shared__ u64t  sW1[200][4];
    __shared__ float sK2S[9][8];
    __shared__ float sC0[8][6][72];
    __shared__ float sC1[8][4][68];

    int tid = threadIdx.x;
    int b   = blockIdx.y;
    int seg = blockIdx.x;
    int side = seg >> 3, s = seg & 7;
    bool bandIsX = (side >= 2);
    bool hi = (side & 1);
    int band_base  = hi ? 504 : 0;
    int g0c = hi ? 506 : 0;
    int g1  = hi ? 508 : 0;
    int g2  = hi ? 509 : 0;
    int along_base = bandIsX ? (s*64 - 2) : (s*64 - 5);

    for (int i = tid; i < 25; i += 256) {
        int ky = i / 5, kx = i % 5;
        int tb = bandIsX ? kx : ky, ta = bandIsX ? ky : kx;
        const float* p = k0 + i*8;
        #pragma unroll
        for (int j = 0; j < 4; j++) sW0[tb*5+ta][j] = pk2(p[2*j], p[2*j+1]);
    }
    for (int i = tid; i < 200; i += 256) {
        int tap = i >> 3, ic = i & 7;
        int ky = tap / 5, kx = tap % 5;
        int tb = bandIsX ? kx : ky, ta = bandIsX ? ky : kx;
        const float* p = k1 + i*8;
        #pragma unroll
        for (int j = 0; j < 4; j++) sW1[(tb*5+ta)*8+ic][j] = pk2(p[2*j], p[2*j+1]);
    }
    for (int i = tid; i < 72; i += 256) {
        int tap = i >> 3, ic = i & 7;
        int ry = tap / 3, rx = tap % 3;
        int tb = bandIsX ? rx : ry, ta = bandIsX ? ry : rx;
        float ssum = 0.f;
        #pragma unroll
        for (int oc = 0; oc < 16; oc++) ssum += c2[i*16 + oc];
        sK2S[tb*3+ta][ic] = ssum;
    }

    const float* up = u + b*(HH*WW);
    for (int i = tid; i < 8*74; i += 256) {
        int bp = i / 74, a = i % 74;
        int gb = band_base + bp, ga = along_base + a;
        int y = bandIsX ? ga : gb, x = bandIsX ? gb : ga;
        sU[bp][a] = ((unsigned)y < 512u && (unsigned)x < 512u) ? up[y*512+x] : 0.f;
    }
    __syncthreads();

    for (int i = tid; i < 420; i += 256) {
        int bp = i / 70, j = i % 70;
        int a = j + 2;
        int ga = along_base + a;
        u64t acc[4] = {0,0,0,0};
        if ((unsigned)ga < 512u) {
            #pragma unroll
            for (int kb = 0; kb < 5; kb++) {
                int bu = g0c + bp + kb - 2 - band_base;
                if ((unsigned)bu < 8u) {
                    #pragma unroll
                    for (int ka = 0; ka < 5; ka++) {
                        float v = sU[bu][a + ka - 2];
                        u64t v2 = pk2(v, v);
                        const u64t* w = sW0[kb*5+ka];
                        acc[0]=fma2(v2,w[0],acc[0]); acc[1]=fma2(v2,w[1],acc[1]);
                        acc[2]=fma2(v2,w[2],acc[2]); acc[3]=fma2(v2,w[3],acc[3]);
                    }
                }
            }
        }
        #pragma unroll
        for (int q = 0; q < 4; q++) {
            float lo, hh; upk2(acc[q], lo, hh);
            sC0[2*q][bp][j] = lo; sC0[2*q+1][bp][j] = hh;
        }
    }
    __syncthreads();

    for (int i = tid; i < 264; i += 256) {
        int bp = i / 66, j = i % 66;
        int a = j + 4;
        int ga = along_base + a;
        u64t acc[4] = {0,0,0,0};
        if ((unsigned)ga < 512u) {
            #pragma unroll
            for (int kb = 0; kb < 5; kb++) {
                int i0 = g1 + bp + kb - 2 - g0c;
                if ((unsigned)i0 < 6u) {
                    #pragma unroll
                    for (int ka = 0; ka < 5; ka++) {
                        int col = a + ka - 4;
                        const u64t* w = &sW1[(kb*5+ka)*8][0];
                        #pragma unroll
                        for (int ic = 0; ic < 8; ic++) {
                            float v = sC0[ic][i0][col];
                            u64t v2 = pk2(v, v);
                            const u64t* wi = w + ic*4;
                            acc[0]=fma2(v2,wi[0],acc[0]); acc[1]=fma2(v2,wi[1],acc[1]);
                            acc[2]=fma2(v2,wi[2],acc[2]); acc[3]=fma2(v2,wi[3],acc[3]);
                        }
                    }
                }
            }
        }
        #pragma unroll
        for (int q = 0; q < 4; q++) {
            float lo, hh; upk2(acc[q], lo, hh);
            sC1[2*q][bp][j] = lo; sC1[2*q+1][bp][j] = hh;
        }
    }
    __syncthreads();

    float* kpre = g_kpre + b*(HH*WW);
    for (int i = tid; i < 192; i += 256) {
        int bp = i / 64, j = i % 64;
        int a = j + 5;
        int ga = along_base + a;
        int gb = g2 + bp;
        if (bandIsX && (ga < 3 || ga >= 509)) continue;
        float ssum = 0.f;
        #pragma unroll
        for (int kb = 0; kb < 3; kb++) {
            int i1 = gb + kb - 1 - g1;
            if ((unsigned)i1 < 4u) {
                #pragma unroll
                for (int ka = 0; ka < 3; ka++) {
                    int col = a + ka - 5;
                    #pragma unroll
                    for (int ic = 0; ic < 8; ic++)
                        ssum = fmaf(sC1[ic][i1][col], sK2S[kb*3+ka][ic], ssum);
                }
            }
        }
        int y = bandIsX ? ga : gb, x = bandIsX ? gb : ga;
        kpre[y*512+x] = ssum * __ldg(kap + y*512 + x);
    }
}

// ---------------- fused final, restructured for occupancy ----------------
// Phases strictly separated by barriers; sBuf reused (img tile -> kpre tile).
// grid (16,16,8), block (8,32): thread (tx,ty) -> row y0+ty, cols x0+4tx..+3
__global__ __launch_bounds__(256, 2) void final_k(const float* __restrict__ u,
                                                  const float* __restrict__ img,
                                                  const float* __restrict__ kxw,  // (3,3,1,32)
                                                  const float* __restrict__ kyw,  // (3,3,1,32)
                                                  const float* __restrict__ smw,  // (5,5,1,1)
                                                  float* __restrict__ out)
{
    __shared__ __align__(16) float sBuf[36*40];   // img tile, then kpre tile (stride 40)
    __shared__ float sE[34*35];
    __shared__ u64t  sDP2[72];                    // dup (w,w)
    __shared__ __align__(16) u64t sKXY2[288];     // packed (wx,wy), pairwise LDS.128
    __shared__ u64t  sSM2[25];                    // dup (w,w)

    int b  = blockIdx.z;
    int x0 = blockIdx.x << 5, y0 = blockIdx.y << 5;
    int tx = threadIdx.x, ty = threadIdx.y;
    int tid = ty * 8 + tx;
    int bx = tx << 2;
    int xb = x0 + bx;
    int y  = y0 + ty;
    int base = b * (HH*WW);

    for (int i = tid; i < 288; i += 256) sKXY2[i] = pk2(kxw[i], kyw[i]);
    if (tid < 72) { float w = g_DP[tid]; sDP2[tid] = pk2(w, w); }
    if (tid < 25) { float w = smw[tid]; sSM2[tid] = pk2(w, w); }

    // ---- phase A: image tile ----
    {
        const float* im = img + base;
        for (int i = tid; i < 36*36; i += 256) {
            int r = i / 36, c = i % 36;
            sBuf[r*40 + c] = ldz(im, y0 + r - 2, x0 + c - 2);
        }
    }
    __syncthreads();

    // ---- phase B: edges into sE (34x34, halo 1), 2 positions packed ----
    for (int i = tid; i < 34*17; i += 256) {
        int r = i / 17, c2 = (i % 17) * 2;
        u64t acc[8] = {0,0,0,0,0,0,0,0};
        #pragma unroll
        for (int dy = 0; dy < 3; dy++) {
            const float* row = &sBuf[(r+dy)*40 + c2];
            float v0 = row[0], v1 = row[1], v2 = row[2], v3 = row[3];
            u64t p0 = pk2(v0, v1), p1 = pk2(v1, v2), p2 = pk2(v2, v3);
            const u64t* w = &sDP2[dy*24];
            #pragma unroll
            for (int ch = 0; ch < 8; ch++) {
                acc[ch] = fma2(p0, w[ch], acc[ch]);
                acc[ch] = fma2(p1, w[8+ch], acc[ch]);
                acc[ch] = fma2(p2, w[16+ch], acc[ch]);
            }
        }
        float sA = 0.f, sB = 0.f;
        #pragma unroll
        for (int ch = 0; ch < 8; ch++) {
            float a, bb; upk2(acc[ch], a, bb);
            sA += fmaxf(a, 0.f); sB += fmaxf(bb, 0.f);
        }
        int gy = y0 + r - 1;
        int gx0 = x0 + c2 - 1;
        bool yok = (unsigned)gy < 512u;
        sE[r*35 + c2]   = (yok && (unsigned)gx0 < 512u)     ? __fdividef(sA, 1.f + fabsf(sA)) : 0.f;
        sE[r*35 + c2+1] = (yok && (unsigned)(gx0+1) < 512u) ? __fdividef(sB, 1.f + fabsf(sB)) : 0.f;
    }
    __syncthreads();

    // ---- phase C: overwrite sBuf with kpre tile ----
    {
        const float* kp = g_kpre + base;
        for (int i = tid; i < 36*36; i += 256) {
            int r = i / 36, c = i % 36;
            sBuf[r*40 + c] = ldz(kp, y0 + r - 2, x0 + c - 2);
        }
    }
    __syncthreads();

    // ---- phase D: grad conv, (wx,wy)-packed weights, channel-paired LDS.128 ----
    float gx[4] = {0,0,0,0}, gy[4] = {0,0,0,0};
    {
        // edges neighborhood (3 rows x 6 cols) dup-packed
        u64t D[18];
        #pragma unroll
        for (int dy = 0; dy < 3; dy++)
            #pragma unroll
            for (int j = 0; j < 6; j++) {
                float e = sE[(ty+dy)*35 + bx + j];
                D[dy*6 + j] = pk2(e, e);
            }

        #pragma unroll 1
        for (int c = 0; c < 32; c += 2) {
            u64t a0=0,a1=0,a2=0,a3=0, b0=0,b1=0,b2=0,b3=0;
            #pragma unroll
            for (int t = 0; t < 9; t++) {
                int dy = t / 3, dx = t % 3;
                ulonglong2 w2 = *(const ulonglong2*)&sKXY2[t*32 + c];
                const u64t* Dp = &D[dy*6 + dx];
                a0 = fma2(Dp[0], w2.x, a0);
                a1 = fma2(Dp[1], w2.x, a1);
                a2 = fma2(Dp[2], w2.x, a2);
                a3 = fma2(Dp[3], w2.x, a3);
                b0 = fma2(Dp[0], w2.y, b0);
                b1 = fma2(Dp[1], w2.y, b1);
                b2 = fma2(Dp[2], w2.y, b2);
                b3 = fma2(Dp[3], w2.y, b3);
            }
            float p, q;
            upk2(a0,p,q); gx[0]+=fmaxf(p,0.f); gy[0]+=fmaxf(q,0.f);
            upk2(a1,p,q); gx[1]+=fmaxf(p,0.f); gy[1]+=fmaxf(q,0.f);
            upk2(a2,p,q); gx[2]+=fmaxf(p,0.f); gy[2]+=fmaxf(q,0.f);
            upk2(a3,p,q); gx[3]+=fmaxf(p,0.f); gy[3]+=fmaxf(q,0.f);
            upk2(b0,p,q); gx[0]+=fmaxf(p,0.f); gy[0]+=fmaxf(q,0.f);
            upk2(b1,p,q); gx[1]+=fmaxf(p,0.f); gy[1]+=fmaxf(q,0.f);
            upk2(b2,p,q); gx[2]+=fmaxf(p,0.f); gy[2]+=fmaxf(q,0.f);
            upk2(b3,p,q); gx[3]+=fmaxf(p,0.f); gy[3]+=fmaxf(q,0.f);
        }
    }

    // ---- phase E: smoother conv5x5 from kpre tile in smem ----
    float ka[4];
    {
        u64t kaccA = 0ULL, kaccB = 0ULL;
        #pragma unroll
        for (int dy = 0; dy < 5; dy++) {
            const float* row = &sBuf[(ty+dy)*40 + bx];
            float4 va = *(const float4*)row;
            float4 vb = *(const float4*)(row + 4);
            float P0=va.x,P1=va.y,P2=va.z,P3=va.w,P4=vb.x,P5=vb.y,P6=vb.z,P7=vb.w;
            u64t pp0=pk2(P0,P1), pp1=pk2(P1,P2), pp2=pk2(P2,P3), pp3=pk2(P3,P4),
                 pp4=pk2(P4,P5), pp5=pk2(P5,P6), pp6=pk2(P6,P7);
            const u64t* w = &sSM2[dy*5];
            kaccA = fma2(pp0, w[0], kaccA); kaccB = fma2(pp2, w[0], kaccB);
            kaccA = fma2(pp1, w[1], kaccA); kaccB = fma2(pp3, w[1], kaccB);
            kaccA = fma2(pp2, w[2], kaccA); kaccB = fma2(pp4, w[2], kaccB);
            kaccA = fma2(pp3, w[3], kaccA); kaccB = fma2(pp5, w[3], kaccB);
            kaccA = fma2(pp4, w[4], kaccA); kaccB = fma2(pp6, w[4], kaccB);
        }
        upk2(kaccA, ka[0], ka[1]);
        upk2(kaccB, ka[2], ka[3]);
    }

    // ---- phase F: finite differences + combine ----
    const float* up = u + base;
    float4 uc4 = *(const float4*)&up[y*512 + xb];
    float uc[4] = {uc4.x, uc4.y, uc4.z, uc4.w};
    float ul0 = (xb > 0) ? __ldg(&up[y*512 + xb - 1]) : 0.f;
    float ul[4] = {ul0, uc[0], uc[1], uc[2]};
    float ud[4];
    if (y < 511) {
        float4 d4 = *(const float4*)&up[(y+1)*512 + xb];
        ud[0] = d4.x; ud[1] = d4.y; ud[2] = d4.z; ud[3] = d4.w;
    } else {
        ud[0] = ud[1] = ud[2] = ud[3] = 0.f;
    }

    float o[4];
    #pragma unroll
    for (int k = 0; k < 4; k++) {
        float ec = sE[(ty+1)*35 + bx + k + 1];
        o[k] = uc[k] + gx[k]*(uc[k]-ul[k]) + gy[k]*(uc[k]-ud[k]) + ec + ka[k];
    }
    *(float4*)&out[base + y*512 + xb] = make_float4(o[0], o[1], o[2], o[3]);
}

// ---------------- launch ----------------
extern "C" void kernel_launch(void* const* d_in, const int* in_sizes, int n_in,
                              void* d_out, int out_size)
{
    const float* u   = (const float*)d_in[0];
    const float* img = (const float*)d_in[1];
    const float* kx  = (const float*)d_in[2];
    const float* ky  = (const float*)d_in[3];
    const float* dw  = (const float*)d_in[4];
    const float* pw  = (const float*)d_in[5];
    const float* c0k = (const float*)d_in[6];
    const float* c1k = (const float*)d_in[7];
    const float* c2k = (const float*)d_in[8];
    const float* smk = (const float*)d_in[9];
    const float* kap = (const float*)d_in[10];
    float* out = (float*)d_out;

    static cudaStream_t side = nullptr;
    static cudaEvent_t evF = nullptr, evJ = nullptr;
    if (!side) {
        cudaStreamCreateWithFlags(&side, cudaStreamNonBlocking);
        cudaEventCreateWithFlags(&evF, cudaEventDisableTiming);
        cudaEventCreateWithFlags(&evJ, cudaEventDisableTiming);
    }

    // fork at start: boundary depends only on inputs (computes its own K2S)
    cudaEventRecord(evF, 0);
    cudaStreamWaitEvent(side, evF, 0);
    boundary_k<<<dim3(32, BB), 256, 0, side>>>(u, c0k, c1k, c2k, kap);
    cudaEventRecord(evJ, side);

    // main: setup -> kc (interior kappa); boundary hides underneath
    setup_k<<<1, 128>>>(dw, pw, c2k, c0k, c1k);
    kc_k<<<dim3(16, 16, 8), dim3(8, 32)>>>(u, kap);

    // join: final needs full g_kpre (kc interior + boundary band)
    cudaStreamWaitEvent(0, evJ, 0);
    final_k<<<dim3(16, 16, 8), dim3(8, 32)>>>(u, img, kx, ky, smk, out);
}